// round 13
// baseline (speedup 1.0000x reference)
#include <cuda_runtime.h>

// Problem constants: N=1024 agents, H=64 hidden.
#define Nn 1024
#define Hh 64
#define EE (Nn * (Nn - 1))   // 1047552 edges

// Factored first layer + relu-elimination scalars:
//   gA[i][k] = b1[k] + sum_c emb[i][c] * W1[c][k]
//   gB[j][k] =         sum_c emb[j][c] * W1[64+c][k]
//   gGamma[i] = b2 + 0.5 * <W2, gA[i]>,   gDelta[j] = 0.5 * <W2, gB[j]>
__device__ float gA[Nn * Hh];
__device__ float gB[Nn * Hh];
__device__ float gGamma[Nn];
__device__ float gDelta[Nn];

// ---- packed f32x2 add (sm_10x) ---------------------------------------------
__device__ __forceinline__ float2 add2(float2 a, float2 b) {
    float2 d;
    asm("add.rn.f32x2 %0, %1, %2;"
        : "=l"(*reinterpret_cast<unsigned long long*>(&d))
        : "l"(*reinterpret_cast<const unsigned long long*>(&a)),
          "l"(*reinterpret_cast<const unsigned long long*>(&b)));
    return d;
}

// ---------------------------------------------------------------------------
// Kernel 1: gA/gB = emb @ [W1_top | W1_bot] (W1 staged in SMEM), plus
// gGamma/gDelta via in-warp dot + butterfly reduce. 128 CTAs x 256 threads.
// Fires the PDL trigger at entry: the pair kernel may begin its
// prep-independent preamble (index planes) immediately.
// ---------------------------------------------------------------------------
__global__ void __launch_bounds__(256) prep_kernel(const float* __restrict__ emb,
                                                   const float* __restrict__ W1,
                                                   const float* __restrict__ b1,
                                                   const float* __restrict__ W2,
                                                   const float* __restrict__ b2ptr) {
    cudaTriggerProgrammaticLaunchCompletion();

    __shared__ float sW1[128 * 64];   // 32 KB

    const int t = threadIdx.x;
#pragma unroll
    for (int q = t; q < 2048; q += 256)
        reinterpret_cast<float4*>(sW1)[q] = reinterpret_cast<const float4*>(W1)[q];
    __syncthreads();

    const int row = blockIdx.x * 8 + (t >> 5);
    const int lane = t & 31;
    const int m = lane * 4;
    const int half = m >> 6;
    const int k = m & 63;
    const float* w1base = sW1 + half * Hh * Hh;

    float acc0 = 0.f, acc1 = 0.f, acc2 = 0.f, acc3 = 0.f;
#pragma unroll
    for (int c = 0; c < Hh; c += 4) {
        const float4 e4 = *reinterpret_cast<const float4*>(emb + row * Hh + c);
        const float4 w0 = *reinterpret_cast<const float4*>(w1base + (c + 0) * Hh + k);
        const float4 w1v = *reinterpret_cast<const float4*>(w1base + (c + 1) * Hh + k);
        const float4 w2v = *reinterpret_cast<const float4*>(w1base + (c + 2) * Hh + k);
        const float4 w3v = *reinterpret_cast<const float4*>(w1base + (c + 3) * Hh + k);
        acc0 = fmaf(e4.x, w0.x, acc0); acc0 = fmaf(e4.y, w1v.x, acc0);
        acc0 = fmaf(e4.z, w2v.x, acc0); acc0 = fmaf(e4.w, w3v.x, acc0);
        acc1 = fmaf(e4.x, w0.y, acc1); acc1 = fmaf(e4.y, w1v.y, acc1);
        acc1 = fmaf(e4.z, w2v.y, acc1); acc1 = fmaf(e4.w, w3v.y, acc1);
        acc2 = fmaf(e4.x, w0.z, acc2); acc2 = fmaf(e4.y, w1v.z, acc2);
        acc2 = fmaf(e4.z, w2v.z, acc2); acc2 = fmaf(e4.w, w3v.z, acc2);
        acc3 = fmaf(e4.x, w0.w, acc3); acc3 = fmaf(e4.y, w1v.w, acc3);
        acc3 = fmaf(e4.z, w2v.w, acc3); acc3 = fmaf(e4.w, w3v.w, acc3);
    }

    float4 o;
    if (half == 0) {
        const float4 bb = *reinterpret_cast<const float4*>(b1 + k);
        o.x = acc0 + bb.x; o.y = acc1 + bb.y; o.z = acc2 + bb.z; o.w = acc3 + bb.w;
        *reinterpret_cast<float4*>(&gA[row * Hh + k]) = o;
    } else {
        o.x = acc0; o.y = acc1; o.z = acc2; o.w = acc3;
        *reinterpret_cast<float4*>(&gB[row * Hh + k]) = o;
    }

    const float4 wv = *reinterpret_cast<const float4*>(W2 + k);
    float part = o.x * wv.x + o.y * wv.y + o.z * wv.z + o.w * wv.w;
#pragma unroll
    for (int off = 8; off > 0; off >>= 1)
        part += __shfl_xor_sync(0xffffffffu, part, off);
    if (lane == 0)  gGamma[row] = b2ptr[0] + 0.5f * part;
    if (lane == 16) gDelta[row] = 0.5f * part;
}

// ---------------------------------------------------------------------------
// Kernel 2: per-pair MLP, relu eliminated:
//   x(i,j) = gGamma[i] + gDelta[j] + sum_k (W2[k]/2) * |A_ik + B_jk|
// Launched with PDL: starts while prep is still running, writes the i/j
// index planes + stages sW2 (prep-independent), THEN gridsyncs on prep and
// does the tile compute. Grid 32x32 = 1024 CTAs, 128 threads, bounds(128,7).
// Tile 32x32, 2x4 micro-tile (tx=t&7, ty=t>>3):
//   i = i0 + ty + 16*ii (ii<2),  j = j0 + tx + 8*jj (jj<4).
// Bank analysis (TPAD=76, quad = 12*row mod 32): B rows tx+8jj -> 8 distinct
// quads; A rows broadcast per 8-lane phase -> all LDS.128 conflict-free.
// Sigmoid uses __fdividef (MUFU.RCP) instead of the IEEE FDIV sequence.
// ---------------------------------------------------------------------------
#define TSI 32
#define TSJ 32
#define TPAD 76

__global__ void __launch_bounds__(128, 7) pair_kernel(const float* __restrict__ W2,
                                                      float* __restrict__ out) {
    __shared__ float sA[TSI * TPAD];
    __shared__ float sB[TSJ * TPAD];
    __shared__ float sW2[64];    // pre-scaled by 0.5
    __shared__ float sGam[TSI];
    __shared__ float sDel[TSJ];

    const int t = threadIdx.x;
    const int tx = t & 7;
    const int ty = t >> 3;
    const int i0 = blockIdx.y * TSI;
    const int j0 = blockIdx.x * TSJ;

    // ---- Prep-independent preamble (overlaps prep under PDL) ----
#pragma unroll
    for (int ii = 0; ii < 2; ii++) {
        const int i = i0 + ty + 16 * ii;
#pragma unroll
        for (int jj = 0; jj < 4; jj++) {
            const int j = j0 + tx + 8 * jj;
            if (j == i) continue;
            const int e = i * (Nn - 1) + j - (j > i ? 1 : 0);
            out[e] = (float)i;
            out[EE + e] = (float)j;
        }
    }
    if (t < 64) sW2[t] = 0.5f * W2[t];

    // ---- Wait for prep's gA/gB/gamma/delta ----
    cudaGridDependencySynchronize();

#pragma unroll
    for (int q = t; q < 1024; q += 128) {
        if (q < 512) {
            const int r = q >> 4, c4 = (q & 15) * 4;
            *reinterpret_cast<float4*>(&sA[r * TPAD + c4]) =
                *reinterpret_cast<const float4*>(&gA[(i0 + r) * Hh + c4]);
        } else {
            const int q2 = q - 512;
            const int r = q2 >> 4, c4 = (q2 & 15) * 4;
            *reinterpret_cast<float4*>(&sB[r * TPAD + c4]) =
                *reinterpret_cast<const float4*>(&gB[(j0 + r) * Hh + c4]);
        }
    }
    if (t < 32)       sGam[t] = gGamma[i0 + t];
    else if (t < 64)  sDel[t - 32] = gDelta[j0 + (t - 32)];
    __syncthreads();

    float acc[2][4] = {};

    const float* aRow0 = &sA[ty * TPAD];
    const float* aRow1 = &sA[(ty + 16) * TPAD];
    const float* bRow0 = &sB[tx * TPAD];
    const float* bRow1 = &sB[(tx + 8) * TPAD];
    const float* bRow2 = &sB[(tx + 16) * TPAD];
    const float* bRow3 = &sB[(tx + 24) * TPAD];

#pragma unroll
    for (int k = 0; k < Hh; k += 4) {
        const float4 wq = *reinterpret_cast<const float4*>(&sW2[k]);
        const float4 av[2] = {
            *reinterpret_cast<const float4*>(aRow0 + k),
            *reinterpret_cast<const float4*>(aRow1 + k)
        };
        const float4 bv[4] = {
            *reinterpret_cast<const float4*>(bRow0 + k),
            *reinterpret_cast<const float4*>(bRow1 + k),
            *reinterpret_cast<const float4*>(bRow2 + k),
            *reinterpret_cast<const float4*>(bRow3 + k)
        };
#pragma unroll
        for (int ii = 0; ii < 2; ii++) {
            const float2 a01 = *reinterpret_cast<const float2*>(&av[ii].x);
            const float2 a23 = *reinterpret_cast<const float2*>(&av[ii].z);
#pragma unroll
            for (int jj = 0; jj < 4; jj++) {
                const float2 b01 = *reinterpret_cast<const float2*>(&bv[jj].x);
                const float2 b23 = *reinterpret_cast<const float2*>(&bv[jj].z);
                const float2 t01 = add2(a01, b01);
                const float2 t23 = add2(a23, b23);
                float a = acc[ii][jj];
                a = fmaf(fabsf(t01.x), wq.x, a);
                a = fmaf(fabsf(t01.y), wq.y, a);
                a = fmaf(fabsf(t23.x), wq.z, a);
                a = fmaf(fabsf(t23.y), wq.w, a);
                acc[ii][jj] = a;
            }
        }
    }

#pragma unroll
    for (int ii = 0; ii < 2; ii++) {
        const int i = i0 + ty + 16 * ii;
        const float gi = sGam[ty + 16 * ii];
#pragma unroll
        for (int jj = 0; jj < 4; jj++) {
            const int j = j0 + tx + 8 * jj;
            if (j == i) continue;
            const int e = i * (Nn - 1) + j - (j > i ? 1 : 0);
            const float x = acc[ii][jj] + gi + sDel[tx + 8 * jj];
            const float ex = __expf(-x);
            out[2 * EE + e] = __fdividef(1.0f, 1.0f + ex);
        }
    }
}

extern "C" void kernel_launch(void* const* d_in, const int* in_sizes, int n_in,
                              void* d_out, int out_size) {
    const float* emb = (const float*)d_in[0];  // [1024, 64]
    const float* W1  = (const float*)d_in[1];  // [128, 64]
    const float* b1  = (const float*)d_in[2];  // [64]
    const float* W2  = (const float*)d_in[3];  // [64, 1]
    const float* b2  = (const float*)d_in[4];  // [1]
    float* out = (float*)d_out;

    prep_kernel<<<128, 256>>>(emb, W1, b1, W2, b2);

    // Pair kernel with Programmatic Dependent Launch: it starts while prep
    // runs, does prep-independent work, then gridsyncs on prep completion.
    cudaLaunchAttribute attrs[1];
    attrs[0].id = cudaLaunchAttributeProgrammaticStreamSerialization;
    attrs[0].val.programmaticStreamSerializationAllowed = 1;
    cudaLaunchConfig_t cfg = {};
    cfg.gridDim = dim3(32, 32);
    cfg.blockDim = dim3(128);
    cfg.dynamicSmemBytes = 0;
    cfg.stream = 0;
    cfg.attrs = attrs;
    cfg.numAttrs = 1;
    cudaLaunchKernelEx(&cfg, pair_kernel, (const float*)W2, out);
}

// round 14
// speedup vs baseline: 1.4877x; 1.4877x over previous
#include <cuda_runtime.h>

// Problem constants: N=1024 agents, H=64 hidden.
#define Nn 1024
#define Hh 64
#define EE (Nn * (Nn - 1))   // 1047552 edges

// Factored first layer + relu-elimination scalars:
//   gA[i][k] = b1[k] + sum_c emb[i][c] * W1[c][k]
//   gB[j][k] =         sum_c emb[j][c] * W1[64+c][k]
//   gGamma[i] = b2 + 0.5 * <W2, gA[i]>,   gDelta[j] = 0.5 * <W2, gB[j]>
__device__ float gA[Nn * Hh];
__device__ float gB[Nn * Hh];
__device__ float gGamma[Nn];
__device__ float gDelta[Nn];

// ---------------------------------------------------------------------------
// Kernel 1: gA/gB = emb @ [W1_top | W1_bot] (W1 staged in SMEM), plus
// gGamma/gDelta via in-warp dot + butterfly reduce. 128 CTAs x 256 threads;
// warp = one emb row, lanes cover the 128 output cols in float4 quads.
// ---------------------------------------------------------------------------
__global__ void __launch_bounds__(256) prep_kernel(const float* __restrict__ emb,
                                                   const float* __restrict__ W1,
                                                   const float* __restrict__ b1,
                                                   const float* __restrict__ W2,
                                                   const float* __restrict__ b2ptr) {
    __shared__ float sW1[128 * 64];   // 32 KB

    const int t = threadIdx.x;
#pragma unroll
    for (int q = t; q < 2048; q += 256)
        reinterpret_cast<float4*>(sW1)[q] = reinterpret_cast<const float4*>(W1)[q];
    __syncthreads();

    const int row = blockIdx.x * 8 + (t >> 5);
    const int lane = t & 31;
    const int m = lane * 4;
    const int half = m >> 6;
    const int k = m & 63;
    const float* w1base = sW1 + half * Hh * Hh;

    float acc0 = 0.f, acc1 = 0.f, acc2 = 0.f, acc3 = 0.f;
#pragma unroll
    for (int c = 0; c < Hh; c += 4) {
        const float4 e4 = *reinterpret_cast<const float4*>(emb + row * Hh + c);
        const float4 w0 = *reinterpret_cast<const float4*>(w1base + (c + 0) * Hh + k);
        const float4 w1v = *reinterpret_cast<const float4*>(w1base + (c + 1) * Hh + k);
        const float4 w2v = *reinterpret_cast<const float4*>(w1base + (c + 2) * Hh + k);
        const float4 w3v = *reinterpret_cast<const float4*>(w1base + (c + 3) * Hh + k);
        acc0 = fmaf(e4.x, w0.x, acc0); acc0 = fmaf(e4.y, w1v.x, acc0);
        acc0 = fmaf(e4.z, w2v.x, acc0); acc0 = fmaf(e4.w, w3v.x, acc0);
        acc1 = fmaf(e4.x, w0.y, acc1); acc1 = fmaf(e4.y, w1v.y, acc1);
        acc1 = fmaf(e4.z, w2v.y, acc1); acc1 = fmaf(e4.w, w3v.y, acc1);
        acc2 = fmaf(e4.x, w0.z, acc2); acc2 = fmaf(e4.y, w1v.z, acc2);
        acc2 = fmaf(e4.z, w2v.z, acc2); acc2 = fmaf(e4.w, w3v.z, acc2);
        acc3 = fmaf(e4.x, w0.w, acc3); acc3 = fmaf(e4.y, w1v.w, acc3);
        acc3 = fmaf(e4.z, w2v.w, acc3); acc3 = fmaf(e4.w, w3v.w, acc3);
    }

    float4 o;
    if (half == 0) {
        const float4 bb = *reinterpret_cast<const float4*>(b1 + k);
        o.x = acc0 + bb.x; o.y = acc1 + bb.y; o.z = acc2 + bb.z; o.w = acc3 + bb.w;
        *reinterpret_cast<float4*>(&gA[row * Hh + k]) = o;
    } else {
        o.x = acc0; o.y = acc1; o.z = acc2; o.w = acc3;
        *reinterpret_cast<float4*>(&gB[row * Hh + k]) = o;
    }

    const float4 wv = *reinterpret_cast<const float4*>(W2 + k);
    float part = o.x * wv.x + o.y * wv.y + o.z * wv.z + o.w * wv.w;
#pragma unroll
    for (int off = 8; off > 0; off >>= 1)
        part += __shfl_xor_sync(0xffffffffu, part, off);
    if (lane == 0)  gGamma[row] = b2ptr[0] + 0.5f * part;
    if (lane == 16) gDelta[row] = 0.5f * part;
}

// ---------------------------------------------------------------------------
// Kernel 2: per-pair MLP, relu eliminated, ALL-SCALAR inner math (no packed
// f32x2 asm -> no 64-bit register-pair marshaling MOVs):
//   x(i,j) = gGamma[i] + gDelta[j] + sum_k (W2[k]/2) * |A_ik + B_jk|
// Per pair per k: 1 FADD + 1 FFMA (|t| folded as operand modifier).
// Grid 32x32 = 1024 CTAs, 64 threads, 4x4 micro-tile (16 pairs/thread):
//   tx = t&7, ty = t>>3;  i = i0 + ty + 8*ii,  j = j0 + tx + 8*jj.
// Bank analysis (TPAD=76, quad = 12*row mod 32): rows r+8u walk 8 distinct
// quads; A rows broadcast per 8-lane phase -> all LDS.128 conflict-free.
// Sigmoid: __expf + __fdividef (MUFU path, no IEEE-div sequence).
// __launch_bounds__(64,11): reg cap 90, smem 20KB*11 = 220KB/SM.
// ---------------------------------------------------------------------------
#define TSI 32
#define TSJ 32
#define TPAD 76

__global__ void __launch_bounds__(64, 11) pair_kernel(const float* __restrict__ W2,
                                                      float* __restrict__ out) {
    __shared__ float sA[TSI * TPAD];
    __shared__ float sB[TSJ * TPAD];
    __shared__ float sW2[64];    // pre-scaled by 0.5
    __shared__ float sGam[TSI];
    __shared__ float sDel[TSJ];

    const int t = threadIdx.x;
    const int tx = t & 7;
    const int ty = t >> 3;
    const int i0 = blockIdx.y * TSI;
    const int j0 = blockIdx.x * TSJ;

    // Cooperative tile loads: sA 512 + sB 512 float4 = 1024 / 64 threads = 16 each.
#pragma unroll
    for (int q = t; q < 1024; q += 64) {
        if (q < 512) {
            const int r = q >> 4, c4 = (q & 15) * 4;
            *reinterpret_cast<float4*>(&sA[r * TPAD + c4]) =
                *reinterpret_cast<const float4*>(&gA[(i0 + r) * Hh + c4]);
        } else {
            const int q2 = q - 512;
            const int r = q2 >> 4, c4 = (q2 & 15) * 4;
            *reinterpret_cast<float4*>(&sB[r * TPAD + c4]) =
                *reinterpret_cast<const float4*>(&gB[(j0 + r) * Hh + c4]);
        }
    }
    sW2[t] = 0.5f * W2[t];
    if (t < 32) sGam[t] = gGamma[i0 + t];
    else        sDel[t - 32] = gDelta[j0 + (t - 32)];
    __syncthreads();

    float acc[4][4] = {};

    const float* aBase = &sA[ty * TPAD];
    const float* bBase = &sB[tx * TPAD];

#pragma unroll
    for (int k = 0; k < Hh; k += 4) {
        const float4 wq = *reinterpret_cast<const float4*>(&sW2[k]);
        float4 av[4], bv[4];
#pragma unroll
        for (int u = 0; u < 4; u++)
            av[u] = *reinterpret_cast<const float4*>(aBase + (8 * u) * TPAD + k);
#pragma unroll
        for (int u = 0; u < 4; u++)
            bv[u] = *reinterpret_cast<const float4*>(bBase + (8 * u) * TPAD + k);

#pragma unroll
        for (int ii = 0; ii < 4; ii++) {
#pragma unroll
            for (int jj = 0; jj < 4; jj++) {
                float a = acc[ii][jj];
                a = fmaf(fabsf(av[ii].x + bv[jj].x), wq.x, a);
                a = fmaf(fabsf(av[ii].y + bv[jj].y), wq.y, a);
                a = fmaf(fabsf(av[ii].z + bv[jj].z), wq.z, a);
                a = fmaf(fabsf(av[ii].w + bv[jj].w), wq.w, a);
                acc[ii][jj] = a;
            }
        }
    }

#pragma unroll
    for (int ii = 0; ii < 4; ii++) {
        const int i = i0 + ty + 8 * ii;
        const float gi = sGam[ty + 8 * ii];
#pragma unroll
        for (int jj = 0; jj < 4; jj++) {
            const int j = j0 + tx + 8 * jj;
            if (j == i) continue;
            const int e = i * (Nn - 1) + j - (j > i ? 1 : 0);
            const float x = acc[ii][jj] + gi + sDel[tx + 8 * jj];
            const float ex = __expf(-x);
            out[e] = (float)i;
            out[EE + e] = (float)j;
            out[2 * EE + e] = __fdividef(1.0f, 1.0f + ex);
        }
    }
}

extern "C" void kernel_launch(void* const* d_in, const int* in_sizes, int n_in,
                              void* d_out, int out_size) {
    const float* emb = (const float*)d_in[0];  // [1024, 64]
    const float* W1  = (const float*)d_in[1];  // [128, 64]
    const float* b1  = (const float*)d_in[2];  // [64]
    const float* W2  = (const float*)d_in[3];  // [64, 1]
    const float* b2  = (const float*)d_in[4];  // [1]
    float* out = (float*)d_out;

    prep_kernel<<<128, 256>>>(emb, W1, b1, W2, b2);
    pair_kernel<<<dim3(32, 32), 64>>>(W2, out);
}